// round 15
// baseline (speedup 1.0000x reference)
#include <cuda_runtime.h>
#include <math.h>

#define N_TOTAL 32768
#define F_DIM   128
#define EMB     32
#define G_NUM   32
#define N_PER   1024

#define OFF_SRC 1048576
#define OFF_DST 34603008
#define OFF_W   68157440

__device__ float g_xg[N_TOTAL * EMB];
__device__ float g_sq[N_TOTAL];
__device__ float g_cent[EMB];
__device__ float g_scale;
__device__ float g_part[32 * 32];   // partial column sums

// ---------------------------------------------------------------------------
// K1: xe = x @ W   (32768x128 @ 128x32)
// ---------------------------------------------------------------------------
__global__ __launch_bounds__(256) void k_gemm(const float* __restrict__ x,
                                              const float* __restrict__ W,
                                              float* __restrict__ xe) {
    __shared__ float xs[32 * 129];
    __shared__ float ws[128 * 32];
    const int tid  = threadIdx.x;
    const int row0 = blockIdx.x * 32;

    const float4* xin = (const float4*)(x + (size_t)row0 * F_DIM);
    for (int f = tid; f < 1024; f += 256) {
        float4 v = xin[f];
        int r = f >> 5;
        int c = (f & 31) * 4;
        xs[r * 129 + c + 0] = v.x;
        xs[r * 129 + c + 1] = v.y;
        xs[r * 129 + c + 2] = v.z;
        xs[r * 129 + c + 3] = v.w;
    }
    for (int f = tid; f < 1024; f += 256)
        ((float4*)ws)[f] = ((const float4*)W)[f];
    __syncthreads();

    const int r  = tid >> 3;
    const int e0 = (tid & 7) * 4;
    float a0 = 0.f, a1 = 0.f, a2 = 0.f, a3 = 0.f;
#pragma unroll
    for (int k = 0; k < 128; k++) {
        float xv = xs[r * 129 + k];
        float4 w4 = *(const float4*)&ws[k * 32 + e0];
        a0 = fmaf(xv, w4.x, a0);
        a1 = fmaf(xv, w4.y, a1);
        a2 = fmaf(xv, w4.z, a2);
        a3 = fmaf(xv, w4.w, a3);
    }
    float4 o; o.x = a0; o.y = a1; o.z = a2; o.w = a3;
    *(float4*)&xe[(size_t)(row0 + r) * EMB + e0] = o;
}

// ---------------------------------------------------------------------------
// K2a: partial column sums of xe[:1024] (32 blocks x 32 rows each)
// ---------------------------------------------------------------------------
__global__ __launch_bounds__(1024) void k_stats_a(const float* __restrict__ xe) {
    __shared__ float buf[32][33];
    const int tid = threadIdx.x;
    const int r   = tid >> 5;
    const int d   = tid & 31;
    buf[r][d] = xe[(blockIdx.x * 32 + r) * EMB + d];
    __syncthreads();
    if (tid < 32) {
        float s = 0.f;
        for (int q = 0; q < 32; q++) s += buf[q][tid];
        g_part[blockIdx.x * 32 + tid] = s;
    }
}

// ---------------------------------------------------------------------------
// K2b: centroid from partials, then max|xe[:1024] - c| -> scale
// ---------------------------------------------------------------------------
__global__ __launch_bounds__(1024) void k_stats_b(const float* __restrict__ xe) {
    __shared__ float cent[32];
    __shared__ float wmax[32];
    const int tid = threadIdx.x;
    const int d   = tid & 31;
    const int gsl = tid >> 5;

    if (tid < 32) {
        float t = 0.f;
        for (int q = 0; q < 32; q++) t += g_part[q * 32 + tid];
        float c = t * (1.0f / (float)N_PER);
        cent[tid] = c;
        g_cent[tid] = c;
    }
    __syncthreads();

    const float c = cent[d];
    float m = 0.f;
    for (int r = gsl; r < N_PER; r += 32)
        m = fmaxf(m, fabsf(xe[r * EMB + d] - c));
#pragma unroll
    for (int o = 16; o; o >>= 1)
        m = fmaxf(m, __shfl_xor_sync(0xffffffffu, m, o));
    if ((tid & 31) == 0) wmax[tid >> 5] = m;
    __syncthreads();
    if (tid == 0) {
        float mm = 0.f;
        for (int w = 0; w < 32; w++) mm = fmaxf(mm, wmax[w]);
        g_scale = 0.9f / mm;
    }
}

// ---------------------------------------------------------------------------
// K3: xg = (xe - centroid) * scale ; sq. One warp per row.
// ---------------------------------------------------------------------------
__global__ __launch_bounds__(256) void k_norm(const float* __restrict__ xe) {
    const int warp = blockIdx.x * 8 + (threadIdx.x >> 5);
    const int lane = threadIdx.x & 31;
    const float c  = g_cent[lane];
    const float sc = g_scale;
    float v = (xe[(size_t)warp * EMB + lane] - c) * sc;
    g_xg[(size_t)warp * EMB + lane] = v;
    float s = v * v;
#pragma unroll
    for (int o = 16; o; o >>= 1)
        s += __shfl_xor_sync(0xffffffffu, s, o);
    if (lane == 0) g_sq[warp] = s;
}

// ---------------------------------------------------------------------------
// K4: pairwise -> sigmoid weights + index pattern.
// 64x64 block tile, 256 threads, 4x4 per-thread tile, 4 CTAs/SM.
// Warp tile 16i x 32j: a-load = 4 distinct float4 (1 phase),
// b-load = 8 distinct float4 = 128 B (1 phase). 33% fewer LDS bytes vs R11.
// ---------------------------------------------------------------------------
#define BM 64
#define BN 64
#define STR 68

__global__ __launch_bounds__(256, 4) void k_pair(const float* __restrict__ tempp,
                                                 const float* __restrict__ thrp,
                                                 float* __restrict__ out) {
    __shared__ float xsi[32 * STR];
    __shared__ float xsj[32 * STR];
    __shared__ float sqi[BM];
    __shared__ float sqj[BN];

    const int tid = threadIdx.x;
    const int g   = blockIdx.z;
    const int i0  = blockIdx.y * BM;
    const int j0  = blockIdx.x * BN;
    const int gb  = g * N_PER;

    for (int f = tid; f < 512; f += 256) {
        int row = f & 63;
        int kq  = (f >> 6) * 4;
        float4 vi = *(const float4*)&g_xg[(size_t)(gb + i0 + row) * EMB + kq];
        float4 vj = *(const float4*)&g_xg[(size_t)(gb + j0 + row) * EMB + kq];
        xsi[(kq + 0) * STR + row] = vi.x;
        xsi[(kq + 1) * STR + row] = vi.y;
        xsi[(kq + 2) * STR + row] = vi.z;
        xsi[(kq + 3) * STR + row] = vi.w;
        xsj[(kq + 0) * STR + row] = vj.x;
        xsj[(kq + 1) * STR + row] = vj.y;
        xsj[(kq + 2) * STR + row] = vj.z;
        xsj[(kq + 3) * STR + row] = vj.w;
    }
    if (tid < 64)        sqi[tid]      = g_sq[gb + i0 + tid];
    else if (tid < 128)  sqj[tid - 64] = g_sq[gb + j0 + (tid - 64)];
    __syncthreads();

    // warp tile 16i x 32j: warps 4x2; lane 4(li) x 8(lj)
    const int lane = tid & 31;
    const int w    = tid >> 5;
    const int ia   = (w >> 1) * 16 + (lane >> 3) * 4;   // i offset in tile
    const int ja   = (w & 1) * 32 + (lane & 7) * 4;     // j offset in tile

    float acc[4][4];
#pragma unroll
    for (int r = 0; r < 4; r++)
#pragma unroll
        for (int c = 0; c < 4; c++) acc[r][c] = 0.f;

#pragma unroll
    for (int k = 0; k < 32; k++) {
        float4 a = *(const float4*)&xsi[k * STR + ia];
        float4 b = *(const float4*)&xsj[k * STR + ja];
        acc[0][0] = fmaf(a.x, b.x, acc[0][0]);
        acc[0][1] = fmaf(a.x, b.y, acc[0][1]);
        acc[0][2] = fmaf(a.x, b.z, acc[0][2]);
        acc[0][3] = fmaf(a.x, b.w, acc[0][3]);
        acc[1][0] = fmaf(a.y, b.x, acc[1][0]);
        acc[1][1] = fmaf(a.y, b.y, acc[1][1]);
        acc[1][2] = fmaf(a.y, b.z, acc[1][2]);
        acc[1][3] = fmaf(a.y, b.w, acc[1][3]);
        acc[2][0] = fmaf(a.z, b.x, acc[2][0]);
        acc[2][1] = fmaf(a.z, b.y, acc[2][1]);
        acc[2][2] = fmaf(a.z, b.z, acc[2][2]);
        acc[2][3] = fmaf(a.z, b.w, acc[2][3]);
        acc[3][0] = fmaf(a.w, b.x, acc[3][0]);
        acc[3][1] = fmaf(a.w, b.y, acc[3][1]);
        acc[3][2] = fmaf(a.w, b.z, acc[3][2]);
        acc[3][3] = fmaf(a.w, b.w, acc[3][3]);
    }

    const float T  = *tempp;
    const float th = fabsf(*thrp);
    const float s0 = sqj[ja + 0];
    const float s1 = sqj[ja + 1];
    const float s2 = sqj[ja + 2];
    const float s3 = sqj[ja + 3];
    const float jbase = (float)(gb + j0 + ja);
    const float4 d4 = make_float4(jbase, jbase + 1.f, jbase + 2.f, jbase + 3.f);

#pragma unroll
    for (int r = 0; r < 4; r++) {
        const int i  = i0 + ia + r;
        const float si = sqi[ia + r];
        const float iv = (float)(gb + i);
        const size_t rowoff = (size_t)g * ((size_t)N_PER * N_PER)
                            + (size_t)i * N_PER + j0 + ja;
        float d0 = fmaxf(si + s0 - 2.0f * acc[r][0], 0.0f);
        float d1 = fmaxf(si + s1 - 2.0f * acc[r][1], 0.0f);
        float d2 = fmaxf(si + s2 - 2.0f * acc[r][2], 0.0f);
        float d3 = fmaxf(si + s3 - 2.0f * acc[r][3], 0.0f);
        float4 wv;
        wv.x = 1.0f / (1.0f + __expf(-T * (th - d0)));
        wv.y = 1.0f / (1.0f + __expf(-T * (th - d1)));
        wv.z = 1.0f / (1.0f + __expf(-T * (th - d2)));
        wv.w = 1.0f / (1.0f + __expf(-T * (th - d3)));
        *(float4*)&out[OFF_SRC + rowoff] = make_float4(iv, iv, iv, iv);
        *(float4*)&out[OFF_DST + rowoff] = d4;
        *(float4*)&out[OFF_W   + rowoff] = wv;
    }
}

// ---------------------------------------------------------------------------
// Launch
// ---------------------------------------------------------------------------
extern "C" void kernel_launch(void* const* d_in, const int* in_sizes, int n_in,
                              void* d_out, int out_size) {
    const float* x    = (const float*)d_in[0];
    const float* W    = (const float*)d_in[1];
    const float* temp = (const float*)d_in[2];
    const float* thr  = (const float*)d_in[3];
    float* out = (float*)d_out;

    k_gemm   <<<N_TOTAL / 32, 256>>>(x, W, out);
    k_stats_a<<<32, 1024>>>(out);
    k_stats_b<<<1, 1024>>>(out);
    k_norm   <<<N_TOTAL / 8, 256>>>(out);
    k_pair   <<<dim3(N_PER / BN, N_PER / BM, G_NUM), 256>>>(temp, thr, out);
}